// round 1
// baseline (speedup 1.0000x reference)
#include <cuda_runtime.h>

#define HH 512
#define WW 512
#define NB 8
#define CC 8
#define TS 32
#define IN_TS 36   // TS + 4 (blur halo 2)
#define PTS 34     // TS + 2 (sobel halo 1)

__device__ double g_acc[3];

__device__ __forceinline__ int reflect_i(int t) {
    // reflect-101 for size 512, offsets within +/-2
    if (t < 0) t = -t;
    if (t >= HH) t = 2 * HH - 2 - t;
    return t;
}

__global__ void zero_acc_kernel() {
    g_acc[0] = 0.0; g_acc[1] = 0.0; g_acc[2] = 0.0;
}

__global__ __launch_bounds__(1024, 2)
void fused_loss_kernel(const float* __restrict__ pan,
                       const float* __restrict__ ms,
                       const float* __restrict__ out) {
    __shared__ float s_in[IN_TS][IN_TS];   // one channel of out, reflect-padded
    __shared__ float s_v[TS][IN_TS];       // vertical blur intermediate
    __shared__ float s_mean[IN_TS][IN_TS]; // channel-sum of out, zero-padded
    __shared__ float s_pan[PTS][PTS];      // pan tile, zero-padded
    __shared__ float red[3][32];

    const int tid = threadIdx.x;
    const int tx = tid & 31, ty = tid >> 5;
    const int tileX = blockIdx.x, tileY = blockIdx.y, n = blockIdx.z;
    const int gx0 = tileX * TS - 2, gy0 = tileY * TS - 2;

    // 5-tap Gaussian, sigma=2 (normalized)
    const float gw0 = 0.15246914f, gw1 = 0.22184130f, gw2 = 0.25137913f;

    // ---- load pan tile (zero padded, halo 1) ----
    for (int idx = tid; idx < PTS * PTS; idx += 1024) {
        int y = idx / PTS, x = idx % PTS;
        int gy = tileY * TS - 1 + y, gx = tileX * TS - 1 + x;
        float v = 0.f;
        if (gy >= 0 && gy < HH && gx >= 0 && gx < WW)
            v = pan[(size_t)(n * HH + gy) * WW + gx];
        s_pan[y][x] = v;
    }

    // ---- per-thread staging coordinates (each thread owns <=2 tile slots) ----
    const int y0 = tid / IN_TS, x0 = tid % IN_TS;
    const int i1 = tid + 1024;
    const int y1 = i1 / IN_TS, x1 = i1 % IN_TS;
    const bool has1 = (i1 < IN_TS * IN_TS);

    const int gya = gy0 + y0, gxa = gx0 + x0;
    const int gyb = gy0 + y1, gxb = gx0 + x1;
    const bool ib0 = (gya >= 0 && gya < HH && gxa >= 0 && gxa < WW);
    const bool ib1 = has1 && (gyb >= 0 && gyb < HH && gxb >= 0 && gxb < WW);
    const int ry0 = reflect_i(gya), rx0 = reflect_i(gxa);
    const int ry1 = has1 ? reflect_i(gyb) : 0;
    const int rx1 = has1 ? reflect_i(gxb) : 0;

    float m0 = 0.f, m1 = 0.f;   // register channel-sum accumulators
    float acc1 = 0.f;

    const int oy = tileY * TS + ty;
    const int ox = tileX * TS + tx;

    for (int c = 0; c < CC; ++c) {
        const float* oc = out + (size_t)(n * CC + c) * HH * WW;
        float v0 = oc[(size_t)ry0 * WW + rx0];
        s_in[y0][x0] = v0;
        if (ib0) m0 += v0;
        if (has1) {
            float v1 = oc[(size_t)ry1 * WW + rx1];
            s_in[y1][x1] = v1;
            if (ib1) m1 += v1;
        }
        __syncthreads();

        // vertical pass: 32 out-rows x 36 cols
        for (int idx = tid; idx < TS * IN_TS; idx += 1024) {
            int r = idx / IN_TS, ccol = idx % IN_TS;
            float s = s_in[r    ][ccol] * gw0
                    + s_in[r + 1][ccol] * gw1
                    + s_in[r + 2][ccol] * gw2
                    + s_in[r + 3][ccol] * gw1
                    + s_in[r + 4][ccol] * gw0;
            s_v[r][ccol] = s;
        }
        __syncthreads();

        // horizontal pass + L1 vs ms
        float b = s_v[ty][tx    ] * gw0
                + s_v[ty][tx + 1] * gw1
                + s_v[ty][tx + 2] * gw2
                + s_v[ty][tx + 3] * gw1
                + s_v[ty][tx + 4] * gw0;
        float mval = ms[((size_t)(n * CC + c) * HH + oy) * WW + ox];
        acc1 += fabsf(b - mval);
        // no extra sync needed: next-iter s_in writes race only against this
        // iter's s_v reads (disjoint arrays); s_v rewrite is behind next sync.
    }

    // ---- write channel-sum tile (zero outside image -> sobel zero-padding) ----
    s_mean[y0][x0] = m0;           // m0 stayed 0 if OOB
    if (has1) s_mean[y1][x1] = m1;
    __syncthreads();

    // ---- sobel on mean/8 (zero pad) and pan (zero pad) ----
    const int cy = ty + 2, cx = tx + 2;
    float a00 = s_mean[cy - 1][cx - 1], a01 = s_mean[cy - 1][cx], a02 = s_mean[cy - 1][cx + 1];
    float a10 = s_mean[cy    ][cx - 1],                           a12 = s_mean[cy    ][cx + 1];
    float a20 = s_mean[cy + 1][cx - 1], a21 = s_mean[cy + 1][cx], a22 = s_mean[cy + 1][cx + 1];
    float ogx = ((a02 - a00) + 2.f * (a12 - a10) + (a22 - a20)) * 0.125f;
    float ogy = ((a20 - a00) + 2.f * (a21 - a01) + (a22 - a02)) * 0.125f;

    const int py = ty + 1, px = tx + 1;
    float p00 = s_pan[py - 1][px - 1], p01 = s_pan[py - 1][px], p02 = s_pan[py - 1][px + 1];
    float p10 = s_pan[py    ][px - 1],                          p12 = s_pan[py    ][px + 1];
    float p20 = s_pan[py + 1][px - 1], p21 = s_pan[py + 1][px], p22 = s_pan[py + 1][px + 1];
    float pgx = (p02 - p00) + 2.f * (p12 - p10) + (p22 - p20);
    float pgy = (p20 - p00) + 2.f * (p21 - p01) + (p22 - p02);

    float acc2 = fabsf(ogx - pgx);
    float acc3 = fabsf(ogy - pgy);

    // ---- block reduction ----
    #pragma unroll
    for (int o = 16; o > 0; o >>= 1) {
        acc1 += __shfl_down_sync(0xFFFFFFFFu, acc1, o);
        acc2 += __shfl_down_sync(0xFFFFFFFFu, acc2, o);
        acc3 += __shfl_down_sync(0xFFFFFFFFu, acc3, o);
    }
    if (tx == 0) { red[0][ty] = acc1; red[1][ty] = acc2; red[2][ty] = acc3; }
    __syncthreads();
    if (ty == 0) {
        float a = red[0][tx], b2 = red[1][tx], c2 = red[2][tx];
        #pragma unroll
        for (int o = 16; o > 0; o >>= 1) {
            a  += __shfl_down_sync(0xFFFFFFFFu, a,  o);
            b2 += __shfl_down_sync(0xFFFFFFFFu, b2, o);
            c2 += __shfl_down_sync(0xFFFFFFFFu, c2, o);
        }
        if (tx == 0) {
            atomicAdd(&g_acc[0], (double)a);
            atomicAdd(&g_acc[1], (double)b2);
            atomicAdd(&g_acc[2], (double)c2);
        }
    }
}

__global__ void finalize_kernel(float* __restrict__ o) {
    double loss = g_acc[0] * (1.0 / 16777216.0)
                + (g_acc[1] + g_acc[2]) * (1.0 / 2097152.0);
    o[0] = (float)loss;
}

extern "C" void kernel_launch(void* const* d_in, const int* in_sizes, int n_in,
                              void* d_out, int out_size) {
    // metadata order: pan [8,1,512,512], ms [8,8,512,512], out [8,8,512,512]
    const float* pan = (const float*)d_in[0];
    const float* ms  = (const float*)d_in[1];
    const float* out = (const float*)d_in[2];
    // safety: locate pan by its unique size if order differs
    if (n_in == 3 && in_sizes[0] != 2097152) {
        for (int i = 0; i < 3; ++i) {
            if (in_sizes[i] == 2097152) {
                pan = (const float*)d_in[i];
                int others[2], k = 0;
                for (int j = 0; j < 3; ++j) if (j != i) others[k++] = j;
                ms  = (const float*)d_in[others[0]];
                out = (const float*)d_in[others[1]];
                break;
            }
        }
    }

    zero_acc_kernel<<<1, 1>>>();
    dim3 grid(WW / TS, HH / TS, NB);
    fused_loss_kernel<<<grid, 1024>>>(pan, ms, out);
    finalize_kernel<<<1, 1>>>((float*)d_out);
}

// round 2
// speedup vs baseline: 1.3082x; 1.3082x over previous
#include <cuda_runtime.h>

#define HH 512
#define WW 512
#define NB 8
#define CC 8
#define TS 32
#define IN_TS 36   // TS + 4 (blur halo 2)
#define PTS 34     // TS + 2 (sobel halo 1)

__device__ double g_acc[3];

__device__ __forceinline__ int reflect_i(int t) {
    if (t < 0) t = -t;
    if (t >= HH) t = 2 * HH - 2 - t;
    return t;
}

__global__ void zero_acc_kernel() {
    g_acc[0] = 0.0; g_acc[1] = 0.0; g_acc[2] = 0.0;
}

__global__ __launch_bounds__(1024, 2)
void fused_loss_kernel(const float* __restrict__ pan,
                       const float* __restrict__ ms,
                       const float* __restrict__ out) {
    __shared__ float s_in[IN_TS][IN_TS];   // one channel of out, reflect-padded
    __shared__ float s_v[TS][IN_TS];       // vertical blur intermediate
    __shared__ float s_mean[IN_TS][IN_TS]; // channel-sum of out, zero-padded
    __shared__ float s_pan[PTS][PTS];      // pan tile, zero-padded
    __shared__ float red[3][32];

    const int tid = threadIdx.x;
    const int tx = tid & 31, ty = tid >> 5;
    const int tileX = blockIdx.x, tileY = blockIdx.y, n = blockIdx.z;
    const int gx0 = tileX * TS - 2, gy0 = tileY * TS - 2;
    const size_t HW = (size_t)HH * WW;

    const float gw0 = 0.15246914f, gw1 = 0.22184130f, gw2 = 0.25137913f;

    // ---- load pan tile (zero padded, halo 1) ----
    for (int idx = tid; idx < PTS * PTS; idx += 1024) {
        int y = idx / PTS, x = idx % PTS;
        int gy = tileY * TS - 1 + y, gx = tileX * TS - 1 + x;
        float v = 0.f;
        if (gy >= 0 && gy < HH && gx >= 0 && gx < WW)
            v = pan[(size_t)(n * HH + gy) * WW + gx];
        s_pan[y][x] = v;
    }

    // ---- staging coordinates (each thread owns <=2 tile slots) ----
    const int y0 = tid / IN_TS, x0 = tid % IN_TS;
    const int i1 = tid + 1024;
    const int y1 = i1 / IN_TS, x1 = i1 % IN_TS;
    const bool has1 = (i1 < IN_TS * IN_TS);

    // vertical-pass coordinates (loop-invariant, hoisted)
    const int rv2 = (tid + 1024) / IN_TS, cv2 = (tid + 1024) % IN_TS;
    const bool hasv2 = (tid < TS * IN_TS - 1024);   // tid < 128

    const int gya = gy0 + y0, gxa = gx0 + x0;
    const int gyb = gy0 + y1, gxb = gx0 + x1;
    const bool ib0 = (gya >= 0 && gya < HH && gxa >= 0 && gxa < WW);
    const bool ib1 = has1 && (gyb >= 0 && gyb < HH && gxb >= 0 && gxb < WW);
    const size_t off0 = (size_t)reflect_i(gya) * WW + reflect_i(gxa);
    const size_t off1 = has1 ? ((size_t)reflect_i(gyb) * WW + reflect_i(gxb)) : 0;

    const int oy = tileY * TS + ty;
    const int ox = tileX * TS + tx;

    const float* ocp = out + (size_t)n * CC * HW;               // channel 0 base
    const float* msp = ms + (size_t)n * CC * HW + (size_t)oy * WW + ox;

    float m0 = 0.f, m1 = 0.f;
    float acc1 = 0.f;

    // ---- prologue: prefetch channel 0 ----
    float pv0 = ocp[off0];
    float pv1 = has1 ? ocp[off1] : 0.f;
    float pms = msp[0];

    for (int c = 0; c < CC; ++c) {
        // commit prefetched channel c into smem / accumulators
        s_in[y0][x0] = pv0;
        if (ib0) m0 += pv0;
        if (has1) {
            s_in[y1][x1] = pv1;
            if (ib1) m1 += pv1;
        }
        const float msc = pms;
        __syncthreads();

        // prefetch channel c+1 — LDGs overlap the blur compute below
        if (c + 1 < CC) {
            const float* ocn = ocp + (size_t)(c + 1) * HW;
            pv0 = ocn[off0];
            if (has1) pv1 = ocn[off1];
            pms = msp[(size_t)(c + 1) * HW];
        }

        // vertical pass (hoisted indices; y0 <= 28 < 32 always valid)
        s_v[y0][x0] = s_in[y0    ][x0] * gw0
                    + s_in[y0 + 1][x0] * gw1
                    + s_in[y0 + 2][x0] * gw2
                    + s_in[y0 + 3][x0] * gw1
                    + s_in[y0 + 4][x0] * gw0;
        if (hasv2)
            s_v[rv2][cv2] = s_in[rv2    ][cv2] * gw0
                          + s_in[rv2 + 1][cv2] * gw1
                          + s_in[rv2 + 2][cv2] * gw2
                          + s_in[rv2 + 3][cv2] * gw1
                          + s_in[rv2 + 4][cv2] * gw0;
        __syncthreads();

        // horizontal pass + L1 vs ms
        float b = s_v[ty][tx    ] * gw0
                + s_v[ty][tx + 1] * gw1
                + s_v[ty][tx + 2] * gw2
                + s_v[ty][tx + 3] * gw1
                + s_v[ty][tx + 4] * gw0;
        acc1 += fabsf(b - msc);
    }

    // ---- channel-sum tile (zero outside image -> sobel zero-padding) ----
    s_mean[y0][x0] = m0;
    if (has1) s_mean[y1][x1] = m1;
    __syncthreads();

    // ---- sobel on mean/8 (zero pad) and pan (zero pad) ----
    const int cy = ty + 2, cx = tx + 2;
    float a00 = s_mean[cy - 1][cx - 1], a01 = s_mean[cy - 1][cx], a02 = s_mean[cy - 1][cx + 1];
    float a10 = s_mean[cy    ][cx - 1],                           a12 = s_mean[cy    ][cx + 1];
    float a20 = s_mean[cy + 1][cx - 1], a21 = s_mean[cy + 1][cx], a22 = s_mean[cy + 1][cx + 1];
    float ogx = ((a02 - a00) + 2.f * (a12 - a10) + (a22 - a20)) * 0.125f;
    float ogy = ((a20 - a00) + 2.f * (a21 - a01) + (a22 - a02)) * 0.125f;

    const int py = ty + 1, px = tx + 1;
    float p00 = s_pan[py - 1][px - 1], p01 = s_pan[py - 1][px], p02 = s_pan[py - 1][px + 1];
    float p10 = s_pan[py    ][px - 1],                          p12 = s_pan[py    ][px + 1];
    float p20 = s_pan[py + 1][px - 1], p21 = s_pan[py + 1][px], p22 = s_pan[py + 1][px + 1];
    float pgx = (p02 - p00) + 2.f * (p12 - p10) + (p22 - p20);
    float pgy = (p20 - p00) + 2.f * (p21 - p01) + (p22 - p02);

    float acc2 = fabsf(ogx - pgx);
    float acc3 = fabsf(ogy - pgy);

    // ---- block reduction ----
    #pragma unroll
    for (int o = 16; o > 0; o >>= 1) {
        acc1 += __shfl_down_sync(0xFFFFFFFFu, acc1, o);
        acc2 += __shfl_down_sync(0xFFFFFFFFu, acc2, o);
        acc3 += __shfl_down_sync(0xFFFFFFFFu, acc3, o);
    }
    if (tx == 0) { red[0][ty] = acc1; red[1][ty] = acc2; red[2][ty] = acc3; }
    __syncthreads();
    if (ty == 0) {
        float a = red[0][tx], b2 = red[1][tx], c2 = red[2][tx];
        #pragma unroll
        for (int o = 16; o > 0; o >>= 1) {
            a  += __shfl_down_sync(0xFFFFFFFFu, a,  o);
            b2 += __shfl_down_sync(0xFFFFFFFFu, b2, o);
            c2 += __shfl_down_sync(0xFFFFFFFFu, c2, o);
        }
        if (tx == 0) {
            atomicAdd(&g_acc[0], (double)a);
            atomicAdd(&g_acc[1], (double)b2);
            atomicAdd(&g_acc[2], (double)c2);
        }
    }
}

__global__ void finalize_kernel(float* __restrict__ o) {
    double loss = g_acc[0] * (1.0 / 16777216.0)
                + (g_acc[1] + g_acc[2]) * (1.0 / 2097152.0);
    o[0] = (float)loss;
}

extern "C" void kernel_launch(void* const* d_in, const int* in_sizes, int n_in,
                              void* d_out, int out_size) {
    const float* pan = (const float*)d_in[0];
    const float* ms  = (const float*)d_in[1];
    const float* out = (const float*)d_in[2];
    if (n_in == 3 && in_sizes[0] != 2097152) {
        for (int i = 0; i < 3; ++i) {
            if (in_sizes[i] == 2097152) {
                pan = (const float*)d_in[i];
                int others[2], k = 0;
                for (int j = 0; j < 3; ++j) if (j != i) others[k++] = j;
                ms  = (const float*)d_in[others[0]];
                out = (const float*)d_in[others[1]];
                break;
            }
        }
    }

    zero_acc_kernel<<<1, 1>>>();
    dim3 grid(WW / TS, HH / TS, NB);
    fused_loss_kernel<<<grid, 1024>>>(pan, ms, out);
    finalize_kernel<<<1, 1>>>((float*)d_out);
}

// round 5
// speedup vs baseline: 1.5384x; 1.1759x over previous
#include <cuda_runtime.h>
#include <cstdint>

#define HH 512
#define WW 512
#define NB 8
#define CC 8
#define TS 32
#define IN_TS 36   // TS + 4 (blur halo 2)
#define PTS 34     // TS + 2 (sobel halo 1)
#define NBLK (16 * 16 * 8)   // 2048 blocks

// dynamic smem layout (float indices)
#define SM_OUT   0                      // [8][36*36] = 10368
#define SM_PAN   10368                  // 34*34 = 1156
#define SM_V     11524                  // 32*36 = 1152
#define SM_MEAN  12676                  // 36*36 = 1296
#define SM_RED   13972                  // 192 floats (= 96 doubles) scratch
#define SM_FLAG  (SM_RED + 192)         // 1 float flag
#define SM_FLOATS (SM_FLAG + 4)         // pad
#define SMEM_BYTES (SM_FLOATS * 4)

__device__ float g_part[NBLK * 3];
__device__ unsigned g_ctr = 0;

__device__ __forceinline__ int reflect_i(int t) {
    if (t < 0) t = -t;
    if (t >= HH) t = 2 * HH - 2 - t;
    return t;
}

__device__ __forceinline__ void cp4(uint32_t s, const float* g) {
    asm volatile("cp.async.ca.shared.global [%0], [%1], 4;" :: "r"(s), "l"(g));
}
__device__ __forceinline__ void cp4z(uint32_t s, const float* g, bool inb) {
    int sz = inb ? 4 : 0;
    asm volatile("cp.async.ca.shared.global [%0], [%1], 4, %2;" :: "r"(s), "l"(g), "r"(sz));
}
__device__ __forceinline__ void cp_commit() {
    asm volatile("cp.async.commit_group;" ::: "memory");
}

__global__ __launch_bounds__(1024)
void fused_loss_kernel(const float* __restrict__ pan,
                       const float* __restrict__ ms,
                       const float* __restrict__ out,
                       float* __restrict__ o) {
    extern __shared__ float sm[];
    float* s_out  = sm + SM_OUT;   // 8 channels, 36x36 each, linear
    float* s_pan  = sm + SM_PAN;   // 34x34
    float* s_v    = sm + SM_V;     // 32x36
    float* s_mean = sm + SM_MEAN;  // 36x36
    float* s_red  = sm + SM_RED;
    float* s_flag = sm + SM_FLAG;

    const int tid = threadIdx.x;
    const int tx = tid & 31, ty = tid >> 5;
    const int tileX = blockIdx.x, tileY = blockIdx.y, n = blockIdx.z;
    const int bid = (blockIdx.z * gridDim.y + blockIdx.y) * gridDim.x + blockIdx.x;
    const size_t HW = (size_t)HH * WW;

    const float gw0 = 0.15246914f, gw1 = 0.22184130f, gw2 = 0.25137913f;

    // ---- staging coords ----
    const int gx0 = tileX * TS - 2, gy0 = tileY * TS - 2;
    const int y0 = tid / IN_TS, x0 = tid % IN_TS;
    const int i1 = tid + 1024;
    const bool has1 = (i1 < IN_TS * IN_TS);     // tid < 272
    const int y1 = i1 / IN_TS, x1 = i1 % IN_TS;

    const int gya = gy0 + y0, gxa = gx0 + x0;
    const int gyb = gy0 + y1, gxb = gx0 + x1;
    const bool ib0 = (gya >= 0 && gya < HH && gxa >= 0 && gxa < WW);
    const bool ib1 = has1 && (gyb >= 0 && gyb < HH && gxb >= 0 && gxb < WW);
    const size_t off0 = (size_t)reflect_i(gya) * WW + reflect_i(gxa);
    const size_t off1 = has1 ? ((size_t)reflect_i(gyb) * WW + reflect_i(gxb)) : 0;

    const int oy = tileY * TS + ty;
    const int ox = tileX * TS + tx;
    const float* ocp = out + (size_t)n * CC * HW;
    const float* msp = ms + (size_t)n * CC * HW + (size_t)oy * WW + ox;

    // ---- ms prefetch (8 plain LDGs, earliest in flight) ----
    float msr[CC];
    #pragma unroll
    for (int c = 0; c < CC; ++c) msr[c] = __ldg(msp + (size_t)c * HW);

    // ---- issue all out channels (groups 0..7) then pan (group 8) ----
    const uint32_t sb_out = (uint32_t)__cvta_generic_to_shared(s_out);
    #pragma unroll
    for (int c = 0; c < CC; ++c) {
        const float* oc = ocp + (size_t)c * HW;
        cp4(sb_out + (uint32_t)(c * 1296 + tid) * 4, oc + off0);
        if (has1) cp4(sb_out + (uint32_t)(c * 1296 + i1) * 4, oc + off1);
        cp_commit();
    }
    {
        const uint32_t sb_pan = (uint32_t)__cvta_generic_to_shared(s_pan);
        // slot 0: indices 0..1023
        {
            int py = tid / PTS, px = tid % PTS;
            int gy = tileY * TS - 1 + py, gx = tileX * TS - 1 + px;
            bool inb = (gy >= 0 && gy < HH && gx >= 0 && gx < WW);
            int cgy = inb ? gy : 0, cgx = inb ? gx : 0;
            if (tid < PTS * PTS)
                cp4z(sb_pan + (uint32_t)tid * 4,
                     pan + (size_t)(n * HH + cgy) * WW + cgx, inb);
        }
        // slot 1: indices 1024..1155 (PTS*PTS = 1156 > 1024!)
        {
            int idx = tid + 1024;
            if (idx < PTS * PTS) {
                int py = idx / PTS, px = idx % PTS;
                int gy = tileY * TS - 1 + py, gx = tileX * TS - 1 + px;
                bool inb = (gy >= 0 && gy < HH && gx >= 0 && gx < WW);
                int cgy = inb ? gy : 0, cgx = inb ? gx : 0;
                cp4z(sb_pan + (uint32_t)idx * 4,
                     pan + (size_t)(n * HH + cgy) * WW + cgx, inb);
            }
        }
        cp_commit();
    }

    // vertical slot-2 ownership
    const bool hasv2 = (tid < TS * IN_TS - 1024);   // tid < 128
    const int hbase = ty * IN_TS + tx;

    float acc1 = 0.f;

    #define DO_CHAN(c) do {                                                     \
        asm volatile("cp.async.wait_group %0;" :: "n"(8 - (c)) : "memory");     \
        __syncthreads();                                                        \
        const float* sc = s_out + (c) * 1296;                                   \
        s_v[tid] = sc[tid      ] * gw0 + sc[tid +  36] * gw1                    \
                 + sc[tid +  72] * gw2 + sc[tid + 108] * gw1                    \
                 + sc[tid + 144] * gw0;                                         \
        if (hasv2)                                                              \
            s_v[tid + 1024] = sc[i1      ] * gw0 + sc[i1 +  36] * gw1           \
                            + sc[i1 +  72] * gw2 + sc[i1 + 108] * gw1           \
                            + sc[i1 + 144] * gw0;                               \
        __syncthreads();                                                        \
        float b = s_v[hbase    ] * gw0 + s_v[hbase + 1] * gw1                   \
                + s_v[hbase + 2] * gw2 + s_v[hbase + 3] * gw1                   \
                + s_v[hbase + 4] * gw0;                                         \
        acc1 += fabsf(b - msr[c]);                                              \
    } while (0)

    DO_CHAN(0); DO_CHAN(1); DO_CHAN(2); DO_CHAN(3);
    DO_CHAN(4); DO_CHAN(5); DO_CHAN(6); DO_CHAN(7);
    #undef DO_CHAN

    // ---- channel-sum tile (zero outside image) ----
    float m0 = 0.f, m1 = 0.f;
    if (ib0) {
        #pragma unroll
        for (int c = 0; c < CC; ++c) m0 += s_out[c * 1296 + tid];
    }
    if (ib1) {
        #pragma unroll
        for (int c = 0; c < CC; ++c) m1 += s_out[c * 1296 + i1];
    }
    s_mean[tid] = m0;
    if (has1) s_mean[i1] = m1;
    asm volatile("cp.async.wait_group 0;" ::: "memory");   // pan group
    __syncthreads();

    // ---- sobel on mean/8 (zero pad) and pan (zero pad) ----
    const int mb = (ty + 2) * IN_TS + (tx + 2);
    float a00 = s_mean[mb - IN_TS - 1], a01 = s_mean[mb - IN_TS], a02 = s_mean[mb - IN_TS + 1];
    float a10 = s_mean[mb - 1],                                   a12 = s_mean[mb + 1];
    float a20 = s_mean[mb + IN_TS - 1], a21 = s_mean[mb + IN_TS], a22 = s_mean[mb + IN_TS + 1];
    float ogx = ((a02 - a00) + 2.f * (a12 - a10) + (a22 - a20)) * 0.125f;
    float ogy = ((a20 - a00) + 2.f * (a21 - a01) + (a22 - a02)) * 0.125f;

    const int pb = (ty + 1) * PTS + (tx + 1);
    float p00 = s_pan[pb - PTS - 1], p01 = s_pan[pb - PTS], p02 = s_pan[pb - PTS + 1];
    float p10 = s_pan[pb - 1],                              p12 = s_pan[pb + 1];
    float p20 = s_pan[pb + PTS - 1], p21 = s_pan[pb + PTS], p22 = s_pan[pb + PTS + 1];
    float pgx = (p02 - p00) + 2.f * (p12 - p10) + (p22 - p20);
    float pgy = (p20 - p00) + 2.f * (p21 - p01) + (p22 - p02);

    float acc2 = fabsf(ogx - pgx);
    float acc3 = fabsf(ogy - pgy);

    // ---- block reduction ----
    #pragma unroll
    for (int o2 = 16; o2 > 0; o2 >>= 1) {
        acc1 += __shfl_down_sync(0xFFFFFFFFu, acc1, o2);
        acc2 += __shfl_down_sync(0xFFFFFFFFu, acc2, o2);
        acc3 += __shfl_down_sync(0xFFFFFFFFu, acc3, o2);
    }
    if (tx == 0) { s_red[ty] = acc1; s_red[32 + ty] = acc2; s_red[64 + ty] = acc3; }
    __syncthreads();
    if (ty == 0) {
        float a = s_red[tx], b2 = s_red[32 + tx], c2 = s_red[64 + tx];
        #pragma unroll
        for (int o2 = 16; o2 > 0; o2 >>= 1) {
            a  += __shfl_down_sync(0xFFFFFFFFu, a,  o2);
            b2 += __shfl_down_sync(0xFFFFFFFFu, b2, o2);
            c2 += __shfl_down_sync(0xFFFFFFFFu, c2, o2);
        }
        if (tx == 0) {
            g_part[bid * 3 + 0] = a;
            g_part[bid * 3 + 1] = b2;
            g_part[bid * 3 + 2] = c2;
            __threadfence();
            unsigned old = atomicAdd(&g_ctr, 1u);
            s_flag[0] = (old == NBLK - 1) ? 1.f : 0.f;
        }
    }
    __syncthreads();

    // ---- last block: final reduction over all partials ----
    if (s_flag[0] != 0.f) {
        __threadfence();
        double a = 0.0, b = 0.0, c = 0.0;
        #pragma unroll
        for (int r = 0; r < 2; ++r) {
            int row = tid + r * 1024;
            a += (double)g_part[row * 3 + 0];
            b += (double)g_part[row * 3 + 1];
            c += (double)g_part[row * 3 + 2];
        }
        #pragma unroll
        for (int o2 = 16; o2 > 0; o2 >>= 1) {
            a += __shfl_down_sync(0xFFFFFFFFu, a, o2);
            b += __shfl_down_sync(0xFFFFFFFFu, b, o2);
            c += __shfl_down_sync(0xFFFFFFFFu, c, o2);
        }
        double* dred = (double*)s_red;   // 96 doubles fit in 192-float region
        __syncthreads();
        if (tx == 0) { dred[ty] = a; dred[32 + ty] = b; dred[64 + ty] = c; }
        __syncthreads();
        if (ty == 0) {
            double aa = dred[tx], bb = dred[32 + tx], cc = dred[64 + tx];
            #pragma unroll
            for (int o2 = 16; o2 > 0; o2 >>= 1) {
                aa += __shfl_down_sync(0xFFFFFFFFu, aa, o2);
                bb += __shfl_down_sync(0xFFFFFFFFu, bb, o2);
                cc += __shfl_down_sync(0xFFFFFFFFu, cc, o2);
            }
            if (tx == 0) {
                o[0] = (float)(aa * (1.0 / 16777216.0) + (bb + cc) * (1.0 / 2097152.0));
                g_ctr = 0;   // reset for next graph replay
            }
        }
    }
}

extern "C" void kernel_launch(void* const* d_in, const int* in_sizes, int n_in,
                              void* d_out, int out_size) {
    const float* pan = (const float*)d_in[0];
    const float* ms  = (const float*)d_in[1];
    const float* out = (const float*)d_in[2];
    if (n_in == 3 && in_sizes[0] != 2097152) {
        for (int i = 0; i < 3; ++i) {
            if (in_sizes[i] == 2097152) {
                pan = (const float*)d_in[i];
                int others[2], k = 0;
                for (int j = 0; j < 3; ++j) if (j != i) others[k++] = j;
                ms  = (const float*)d_in[others[0]];
                out = (const float*)d_in[others[1]];
                break;
            }
        }
    }

    static bool attr_done = false;
    if (!attr_done) {
        cudaFuncSetAttribute(fused_loss_kernel,
                             cudaFuncAttributeMaxDynamicSharedMemorySize, SMEM_BYTES);
        attr_done = true;
    }

    dim3 grid(WW / TS, HH / TS, NB);
    fused_loss_kernel<<<grid, 1024, SMEM_BYTES>>>(pan, ms, out, (float*)d_out);
}